// round 11
// baseline (speedup 1.0000x reference)
#include <cuda_runtime.h>
#include <cuda_fp16.h>
#include <cuda_bf16.h>
#include <cstdint>

// ForwardWarp, N=4, C=3, H=1080, W=1920, fp32 in/out.
// Channel-split f16 scratch, zero pad waste (24 atomic B/px):
//   plane01: f16x2(c0,c1)/px -> tap-pair = red.global.add.noftz.v2.f16x2 (8B)
//   plane2 : f16(c2)/px      -> tap-pair = red.global.add.noftz.f16x2   (4B)
// Parity-split buffers (odd pairs go to a 1-pixel-shifted buffer) keep every
// pair access naturally aligned. Finalize sums 4 partials -> fp32 NCHW.
// Per-batch stream pipelining: zero[n] -> scatter[n] -> finalize[n].

#define FW_N 4
#define FW_C 3
#define FW_H 1080
#define FW_W 1920
#define FW_HW (FW_H * FW_W)
#define FW_PIX (FW_N * FW_HW)
#define FW_ODD_STRIDE (FW_HW + 8)          // per-batch odd-slice stride (16B-friendly)

__device__ __align__(128) uint32_t fw01_e[FW_PIX];                  // 33.2 MB
__device__ __align__(128) uint32_t fw01_o[FW_N * FW_ODD_STRIDE];    // 33.2 MB
__device__ __align__(128) uint16_t fw2_e[FW_PIX];                   // 16.6 MB
__device__ __align__(128) uint16_t fw2_o[FW_N * FW_ODD_STRIDE];     // 16.6 MB
// all zero-initialized at module load

// ---------------- per-batch zero (all four planes) ----------------
#define ZERO_BLOCKS 1184
#define ZERO_THREADS 256
__global__ __launch_bounds__(ZERO_THREADS) void fw_zero_kernel(int n)
{
    const uint4 z = make_uint4(0u, 0u, 0u, 0u);
    const int stride = ZERO_BLOCKS * ZERO_THREADS;
    const int t0 = blockIdx.x * ZERO_THREADS + threadIdx.x;

    uint4* a = reinterpret_cast<uint4*>(fw01_e + (size_t)n * FW_HW);
    for (int i = t0; i < FW_HW / 4; i += stride) a[i] = z;
    uint4* b = reinterpret_cast<uint4*>(fw01_o + (size_t)n * FW_ODD_STRIDE);
    for (int i = t0; i < FW_ODD_STRIDE / 4; i += stride) b[i] = z;
    uint4* c = reinterpret_cast<uint4*>(fw2_e + (size_t)n * FW_HW);
    for (int i = t0; i < FW_HW / 8; i += stride) c[i] = z;
    uint4* d = reinterpret_cast<uint4*>(fw2_o + (size_t)n * FW_ODD_STRIDE);
    for (int i = t0; i < FW_ODD_STRIDE / 8; i += stride) d[i] = z;
}

// ---------------- scatter ----------------
__device__ __forceinline__ uint32_t h2u(float a, float b)
{
    __half2 h = __floats2half2_rn(a, b);
    return *reinterpret_cast<const uint32_t*>(&h);
}

__device__ __forceinline__ void red_p01_pair(uint32_t* p, uint32_t v0, uint32_t v1)
{
    asm volatile("red.global.add.noftz.v2.f16x2 [%0], {%1, %2};"
                 :: "l"(p), "r"(v0), "r"(v1) : "memory");
}

__device__ __forceinline__ void red_p01_one(uint32_t* p, uint32_t v)
{
    asm volatile("red.global.add.noftz.f16x2 [%0], %1;"
                 :: "l"(p), "r"(v) : "memory");
}

__device__ __forceinline__ void red_p2_pair(uint16_t* p, uint32_t v)
{
    asm volatile("red.global.add.noftz.f16x2 [%0], %1;"
                 :: "l"(p), "r"(v) : "memory");
}

__device__ __forceinline__ void red_p2_one(uint16_t* p, float v)
{
    __half h = __float2half_rn(v);
    asm volatile("red.global.add.noftz.f16 [%0], %1;"
                 :: "l"(p), "h"(*reinterpret_cast<const uint16_t*>(&h)) : "memory");
}

// Grid: (FW_W/128, FW_H, 1), block 128; batch passed as arg.
__global__ __launch_bounds__(128) void fw_scatter_kernel(
    const float* __restrict__ img,
    const float* __restrict__ flo,
    int n)
{
    const int w = blockIdx.x * 128 + threadIdx.x;
    const int h = blockIdx.y;
    const int hw = h * FW_W + w;

    // flo channel 0 -> column shift, channel 1 -> row shift.
    const float* flo_n = flo + (size_t)n * 2 * FW_HW;
    const float ycol = __ldcs(flo_n + hw);
    const float xrow = __ldcs(flo_n + FW_HW + hw);

    const float xf = floorf(xrow);
    const float yf = floorf(ycol);
    const int ix = (int)xf;
    const int iy = (int)yf;
    const float fx = xrow - xf;   // row frac
    const float fy = ycol - yf;   // col frac

    const float* img_n = img + (size_t)n * FW_C * FW_HW;
    const float c0 = __ldcs(img_n + hw);
    const float c1 = __ldcs(img_n + FW_HW + hw);
    const float c2 = __ldcs(img_n + 2 * FW_HW + hw);

    const float wx0 = 1.0f - fx;
    const float wy0 = 1.0f - fy;

    const int rbase = h + ix;
    const int cc = w + iy;
    const int par = cc & 1;

    uint32_t* __restrict__ p01e = fw01_e + (size_t)n * FW_HW;
    uint32_t* __restrict__ p01o = fw01_o + (size_t)n * FW_ODD_STRIDE;
    uint16_t* __restrict__ p2e  = fw2_e  + (size_t)n * FW_HW;
    uint16_t* __restrict__ p2o  = fw2_o  + (size_t)n * FW_ODD_STRIDE;

    #pragma unroll
    for (int dx = 0; dx < 2; dx++) {
        const int rr = rbase + dx;
        if ((unsigned)rr >= (unsigned)FW_H) continue;
        const float wx = dx ? fx : wx0;
        const float w0 = wx * wy0;   // column cc
        const float w1 = wx * fy;    // column cc + 1
        const int rowoff = rr * FW_W;

        if ((unsigned)cc <= (unsigned)(FW_W - 2)) {
            const int idx = rowoff + cc + par;     // pair base (even in its buffer)
            uint32_t* q01 = par ? (p01o + idx) : (p01e + idx);
            uint16_t* q2  = par ? (p2o + idx)  : (p2e + idx);
            red_p01_pair(q01, h2u(c0 * w0, c1 * w0), h2u(c0 * w1, c1 * w1));
            red_p2_pair(q2, h2u(c2 * w0, c2 * w1));
        } else {
            if ((unsigned)cc < (unsigned)FW_W) {          // cc == W-1: left tap only
                red_p01_one(p01e + rowoff + cc, h2u(c0 * w0, c1 * w0));
                red_p2_one(p2e + rowoff + cc, c2 * w0);
            }
            if ((unsigned)(cc + 1) < (unsigned)FW_W) {    // cc == -1: right tap only
                red_p01_one(p01e + rowoff + cc + 1, h2u(c0 * w1, c1 * w1));
                red_p2_one(p2e + rowoff + cc + 1, c2 * w1);
            }
        }
    }
}

// ---------------- finalize: sum parity planes, f16 -> fp32 NCHW ----------------
// Grid: (FW_W/128, FW_H, 1), block 128; batch passed as arg.
__global__ __launch_bounds__(128) void fw_finalize_kernel(float* __restrict__ out, int n)
{
    const int w = blockIdx.x * 128 + threadIdx.x;
    const int h = blockIdx.y;
    const int hw = h * FW_W + w;

    uint32_t e01, o01;
    uint16_t e2u, o2u;
    asm volatile("ld.global.cs.u32 %0, [%1];" : "=r"(e01) : "l"(fw01_e + (size_t)n * FW_HW + hw));
    asm volatile("ld.global.cs.u32 %0, [%1];" : "=r"(o01) : "l"(fw01_o + (size_t)n * FW_ODD_STRIDE + hw + 1));
    asm volatile("ld.global.cs.u16 %0, [%1];" : "=h"(e2u) : "l"(fw2_e + (size_t)n * FW_HW + hw));
    asm volatile("ld.global.cs.u16 %0, [%1];" : "=h"(o2u) : "l"(fw2_o + (size_t)n * FW_ODD_STRIDE + hw + 1));

    const float2 fe = __half22float2(*reinterpret_cast<const __half2*>(&e01));
    const float2 fo = __half22float2(*reinterpret_cast<const __half2*>(&o01));
    const float r0 = fe.x + fo.x;
    const float r1 = fe.y + fo.y;
    const float r2 = __half2float(*reinterpret_cast<const __half*>(&e2u))
                   + __half2float(*reinterpret_cast<const __half*>(&o2u));

    float* __restrict__ out_n = out + (size_t)n * FW_C * FW_HW;
    asm volatile("st.global.cs.f32 [%0], %1;" :: "l"(out_n + hw),             "f"(r0) : "memory");
    asm volatile("st.global.cs.f32 [%0], %1;" :: "l"(out_n + FW_HW + hw),     "f"(r1) : "memory");
    asm volatile("st.global.cs.f32 [%0], %1;" :: "l"(out_n + 2 * FW_HW + hw), "f"(r2) : "memory");
}

// ---------------- streams/events: created once at static init ----------------
struct FwResources {
    cudaStream_t zs;
    cudaStream_t cs[FW_N];
    cudaEvent_t  root;
    cudaEvent_t  ez[FW_N];
    cudaEvent_t  ef[FW_N];
    FwResources() {
        cudaStreamCreateWithFlags(&zs, cudaStreamNonBlocking);
        cudaEventCreateWithFlags(&root, cudaEventDisableTiming);
        for (int i = 0; i < FW_N; i++) {
            cudaStreamCreateWithFlags(&cs[i], cudaStreamNonBlocking);
            cudaEventCreateWithFlags(&ez[i], cudaEventDisableTiming);
            cudaEventCreateWithFlags(&ef[i], cudaEventDisableTiming);
        }
    }
};
static FwResources g_fw;

extern "C" void kernel_launch(void* const* d_in, const int* in_sizes, int n_in,
                              void* d_out, int out_size)
{
    const float* img = (const float*)d_in[0];
    const float* flo = (const float*)d_in[1];
    float* out = (float*)d_out;

    cudaEventRecord(g_fw.root, 0);
    cudaStreamWaitEvent(g_fw.zs, g_fw.root, 0);

    for (int n = 0; n < FW_N; n++) {
        fw_zero_kernel<<<ZERO_BLOCKS, ZERO_THREADS, 0, g_fw.zs>>>(n);
        cudaEventRecord(g_fw.ez[n], g_fw.zs);
    }

    dim3 sgrid(FW_W / 128, FW_H, 1);
    for (int n = 0; n < FW_N; n++) {
        cudaStreamWaitEvent(g_fw.cs[n], g_fw.ez[n], 0);
        fw_scatter_kernel<<<sgrid, 128, 0, g_fw.cs[n]>>>(img, flo, n);
        fw_finalize_kernel<<<sgrid, 128, 0, g_fw.cs[n]>>>(out, n);
        cudaEventRecord(g_fw.ef[n], g_fw.cs[n]);
    }

    for (int n = 0; n < FW_N; n++)
        cudaStreamWaitEvent(0, g_fw.ef[n], 0);
}

// round 14
// speedup vs baseline: 1.0873x; 1.0873x over previous
#include <cuda_runtime.h>
#include <cuda_fp16.h>
#include <cuda_bf16.h>
#include <cstdint>

// ForwardWarp, N=4, C=3, H=1080, W=1920, fp32 in/out.
// Round-10 kernels (parity-split f16x4 scratch, one 16B v4.f16x2 RED per
// bilinear tap-pair) + 3-stream software pipeline:
//   zs: zero[0..3]   (serial)
//   ss: scatter[0..3](serial)  - scatter[n] waits zero[n]
//   fs: finalize[0..3](serial) - finalize[n] waits scatter[n]
// Serializing the scatters staggers their completions so each finalize hides
// under the next scatter instead of all being exposed at the end (round-10's
// concurrent scatters finished together -> 37us exposed finalize tail).

#define FW_N 4
#define FW_C 3
#define FW_H 1080
#define FW_W 1920
#define FW_HW (FW_H * FW_W)
#define FW_PIX (FW_N * FW_HW)
#define FW_ODD_STRIDE (FW_HW + 2)          // per-batch odd-slice stride (even)

// 8 bytes per pixel: {f16x2(c0,c1), f16x2(c2,0)}
__device__ __align__(128) uint2 fw_even[FW_PIX];                  // 66.4 MB
__device__ __align__(128) uint2 fw_odd[FW_N * FW_ODD_STRIDE];     // 66.4 MB
// both zero-initialized at module load

// ---------------- per-batch zero (both buffers) ----------------
#define ZERO_BLOCKS 1184
#define ZERO_THREADS 256
__global__ __launch_bounds__(ZERO_THREADS) void fw_zero_kernel(int n)
{
    const uint4 z = make_uint4(0u, 0u, 0u, 0u);
    const int stride = ZERO_BLOCKS * ZERO_THREADS;
    const int t0 = blockIdx.x * ZERO_THREADS + threadIdx.x;

    uint4* se = reinterpret_cast<uint4*>(fw_even + (size_t)n * FW_HW);
    for (int i = t0; i < FW_HW / 2; i += stride) se[i] = z;

    uint4* so = reinterpret_cast<uint4*>(fw_odd + (size_t)n * FW_ODD_STRIDE);
    for (int i = t0; i < FW_ODD_STRIDE / 2; i += stride) so[i] = z;
}

// ---------------- scatter ----------------
__device__ __forceinline__ uint32_t h2u(float a, float b)
{
    __half2 h = __floats2half2_rn(a, b);
    return *reinterpret_cast<const uint32_t*>(&h);
}

__device__ __forceinline__ void red_add_v2h2(uint2* p, uint32_t h01, uint32_t h23)
{
    asm volatile("red.global.add.noftz.v2.f16x2 [%0], {%1, %2};"
                 :: "l"(p), "r"(h01), "r"(h23) : "memory");
}

__device__ __forceinline__ void red_add_v4h2(uint2* p, uint32_t a, uint32_t b,
                                             uint32_t c, uint32_t d)
{
    asm volatile("red.global.add.noftz.v4.f16x2 [%0], {%1, %2, %3, %4};"
                 :: "l"(p), "r"(a), "r"(b), "r"(c), "r"(d) : "memory");
}

// Grid: (FW_W/128, FW_H, 1), block 128; batch passed as arg.
__global__ __launch_bounds__(128) void fw_scatter_kernel(
    const float* __restrict__ img,
    const float* __restrict__ flo,
    int n)
{
    const int w = blockIdx.x * 128 + threadIdx.x;
    const int h = blockIdx.y;
    const int hw = h * FW_W + w;

    // flo channel 0 -> column shift, channel 1 -> row shift.
    const float* flo_n = flo + (size_t)n * 2 * FW_HW;
    const float ycol = __ldcs(flo_n + hw);
    const float xrow = __ldcs(flo_n + FW_HW + hw);

    const float xf = floorf(xrow);
    const float yf = floorf(ycol);
    const int ix = (int)xf;
    const int iy = (int)yf;
    const float fx = xrow - xf;   // row frac
    const float fy = ycol - yf;   // col frac

    const float* img_n = img + (size_t)n * FW_C * FW_HW;
    const float c0 = __ldcs(img_n + hw);
    const float c1 = __ldcs(img_n + FW_HW + hw);
    const float c2 = __ldcs(img_n + 2 * FW_HW + hw);

    const float wx0 = 1.0f - fx;
    const float wy0 = 1.0f - fy;

    const int rbase = h + ix;
    const int cc = w + iy;
    const int par = cc & 1;

    uint2* __restrict__ ev_n = fw_even + (size_t)n * FW_HW;
    uint2* __restrict__ od_n = fw_odd + (size_t)n * FW_ODD_STRIDE;

    #pragma unroll
    for (int dx = 0; dx < 2; dx++) {
        const int rr = rbase + dx;
        if ((unsigned)rr >= (unsigned)FW_H) continue;
        const float wx = dx ? fx : wx0;
        const float w0 = wx * wy0;   // column cc
        const float w1 = wx * fy;    // column cc + 1
        const int rowoff = rr * FW_W;

        if ((unsigned)cc <= (unsigned)(FW_W - 2)) {
            uint2* p = par ? (od_n + rowoff + cc + 1) : (ev_n + rowoff + cc);
            red_add_v4h2(p,
                         h2u(c0 * w0, c1 * w0), h2u(c2 * w0, 0.0f),
                         h2u(c0 * w1, c1 * w1), h2u(c2 * w1, 0.0f));
        } else {
            if ((unsigned)cc < (unsigned)FW_W)
                red_add_v2h2(ev_n + rowoff + cc, h2u(c0 * w0, c1 * w0), h2u(c2 * w0, 0.0f));
            if ((unsigned)(cc + 1) < (unsigned)FW_W)
                red_add_v2h2(ev_n + rowoff + cc + 1, h2u(c0 * w1, c1 * w1), h2u(c2 * w1, 0.0f));
        }
    }
}

// ---------------- finalize: sum parity buffers, f16x4 -> fp32 NCHW ----------------
// Grid: (FW_W/128, FW_H, 1), block 128; batch passed as arg.
__global__ __launch_bounds__(128) void fw_finalize_kernel(float* __restrict__ out, int n)
{
    const int w = blockIdx.x * 128 + threadIdx.x;
    const int h = blockIdx.y;
    const int hw = h * FW_W + w;

    const uint2* ep = fw_even + ((size_t)n * FW_HW + hw);
    const uint2* op = fw_odd + ((size_t)n * FW_ODD_STRIDE + hw + 1);

    uint32_t ea, eb, oa, ob;
    asm volatile("ld.global.cs.v2.u32 {%0, %1}, [%2];" : "=r"(ea), "=r"(eb) : "l"(ep));
    asm volatile("ld.global.cs.v2.u32 {%0, %1}, [%2];" : "=r"(oa), "=r"(ob) : "l"(op));

    const float2 e01 = __half22float2(*reinterpret_cast<const __half2*>(&ea));
    const float2 e23 = __half22float2(*reinterpret_cast<const __half2*>(&eb));
    const float2 o01 = __half22float2(*reinterpret_cast<const __half2*>(&oa));
    const float2 o23 = __half22float2(*reinterpret_cast<const __half2*>(&ob));

    float* __restrict__ out_n = out + (size_t)n * FW_C * FW_HW;
    const float r0 = e01.x + o01.x;
    const float r1 = e01.y + o01.y;
    const float r2 = e23.x + o23.x;
    asm volatile("st.global.cs.f32 [%0], %1;" :: "l"(out_n + hw),             "f"(r0) : "memory");
    asm volatile("st.global.cs.f32 [%0], %1;" :: "l"(out_n + FW_HW + hw),     "f"(r1) : "memory");
    asm volatile("st.global.cs.f32 [%0], %1;" :: "l"(out_n + 2 * FW_HW + hw), "f"(r2) : "memory");
}

// ---------------- streams/events: created once at static init ----------------
struct FwResources {
    cudaStream_t zs, ss, fs;
    cudaEvent_t  root;
    cudaEvent_t  ez[FW_N];   // zero[n] done
    cudaEvent_t  es[FW_N];   // scatter[n] done
    cudaEvent_t  efin;       // finalize[3] done
    FwResources() {
        cudaStreamCreateWithFlags(&zs, cudaStreamNonBlocking);
        cudaStreamCreateWithFlags(&ss, cudaStreamNonBlocking);
        cudaStreamCreateWithFlags(&fs, cudaStreamNonBlocking);
        cudaEventCreateWithFlags(&root, cudaEventDisableTiming);
        cudaEventCreateWithFlags(&efin, cudaEventDisableTiming);
        for (int i = 0; i < FW_N; i++) {
            cudaEventCreateWithFlags(&ez[i], cudaEventDisableTiming);
            cudaEventCreateWithFlags(&es[i], cudaEventDisableTiming);
        }
    }
};
static FwResources g_fw;

extern "C" void kernel_launch(void* const* d_in, const int* in_sizes, int n_in,
                              void* d_out, int out_size)
{
    const float* img = (const float*)d_in[0];
    const float* flo = (const float*)d_in[1];
    float* out = (float*)d_out;

    cudaEventRecord(g_fw.root, 0);
    cudaStreamWaitEvent(g_fw.zs, g_fw.root, 0);
    cudaStreamWaitEvent(g_fw.ss, g_fw.root, 0);
    cudaStreamWaitEvent(g_fw.fs, g_fw.root, 0);

    dim3 sgrid(FW_W / 128, FW_H, 1);

    for (int n = 0; n < FW_N; n++) {
        fw_zero_kernel<<<ZERO_BLOCKS, ZERO_THREADS, 0, g_fw.zs>>>(n);
        cudaEventRecord(g_fw.ez[n], g_fw.zs);
    }
    for (int n = 0; n < FW_N; n++) {
        cudaStreamWaitEvent(g_fw.ss, g_fw.ez[n], 0);
        fw_scatter_kernel<<<sgrid, 128, 0, g_fw.ss>>>(img, flo, n);
        cudaEventRecord(g_fw.es[n], g_fw.ss);
    }
    for (int n = 0; n < FW_N; n++) {
        cudaStreamWaitEvent(g_fw.fs, g_fw.es[n], 0);
        fw_finalize_kernel<<<sgrid, 128, 0, g_fw.fs>>>(out, n);
    }
    cudaEventRecord(g_fw.efin, g_fw.fs);
    cudaStreamWaitEvent(0, g_fw.efin, 0);
}

// round 15
// speedup vs baseline: 1.1467x; 1.0546x over previous
#include <cuda_runtime.h>
#include <cuda_fp16.h>
#include <cuda_bf16.h>
#include <cstdint>

// ForwardWarp, N=4, C=3, H=1080, W=1920, fp32 in/out.
// Round-10 structure (best measured): parity-split f16x4 scratch, one 16B
// red.add.noftz.v4.f16x2 per bilinear tap-pair, per-batch concurrent chains
// zero[n] -> scatter[n] -> finalize[n].
// This round: 2px/thread finalize (fewer mem instructions) + priority
// streams (scatter high, finalize low) to win LTS arbitration.

#define FW_N 4
#define FW_C 3
#define FW_H 1080
#define FW_W 1920
#define FW_HW (FW_H * FW_W)
#define FW_PIX (FW_N * FW_HW)
#define FW_ODD_STRIDE (FW_HW + 2)          // per-batch odd-slice stride (even)

// 8 bytes per pixel: {f16x2(c0,c1), f16x2(c2,0)}
__device__ __align__(128) uint2 fw_even[FW_PIX];                  // 66.4 MB
__device__ __align__(128) uint2 fw_odd[FW_N * FW_ODD_STRIDE];     // 66.4 MB
// both zero-initialized at module load

// ---------------- per-batch zero (both buffers) ----------------
#define ZERO_BLOCKS 1184
#define ZERO_THREADS 256
__global__ __launch_bounds__(ZERO_THREADS) void fw_zero_kernel(int n)
{
    const uint4 z = make_uint4(0u, 0u, 0u, 0u);
    const int stride = ZERO_BLOCKS * ZERO_THREADS;
    const int t0 = blockIdx.x * ZERO_THREADS + threadIdx.x;

    uint4* se = reinterpret_cast<uint4*>(fw_even + (size_t)n * FW_HW);
    for (int i = t0; i < FW_HW / 2; i += stride) se[i] = z;

    uint4* so = reinterpret_cast<uint4*>(fw_odd + (size_t)n * FW_ODD_STRIDE);
    for (int i = t0; i < FW_ODD_STRIDE / 2; i += stride) so[i] = z;
}

// ---------------- scatter ----------------
__device__ __forceinline__ uint32_t h2u(float a, float b)
{
    __half2 h = __floats2half2_rn(a, b);
    return *reinterpret_cast<const uint32_t*>(&h);
}

__device__ __forceinline__ void red_add_v2h2(uint2* p, uint32_t h01, uint32_t h23)
{
    asm volatile("red.global.add.noftz.v2.f16x2 [%0], {%1, %2};"
                 :: "l"(p), "r"(h01), "r"(h23) : "memory");
}

__device__ __forceinline__ void red_add_v4h2(uint2* p, uint32_t a, uint32_t b,
                                             uint32_t c, uint32_t d)
{
    asm volatile("red.global.add.noftz.v4.f16x2 [%0], {%1, %2, %3, %4};"
                 :: "l"(p), "r"(a), "r"(b), "r"(c), "r"(d) : "memory");
}

// Grid: (FW_W/128, FW_H, 1), block 128; batch passed as arg.
__global__ __launch_bounds__(128) void fw_scatter_kernel(
    const float* __restrict__ img,
    const float* __restrict__ flo,
    int n)
{
    const int w = blockIdx.x * 128 + threadIdx.x;
    const int h = blockIdx.y;
    const int hw = h * FW_W + w;

    // flo channel 0 -> column shift, channel 1 -> row shift.
    const float* flo_n = flo + (size_t)n * 2 * FW_HW;
    const float ycol = __ldcs(flo_n + hw);
    const float xrow = __ldcs(flo_n + FW_HW + hw);

    const float xf = floorf(xrow);
    const float yf = floorf(ycol);
    const int ix = (int)xf;
    const int iy = (int)yf;
    const float fx = xrow - xf;   // row frac
    const float fy = ycol - yf;   // col frac

    const float* img_n = img + (size_t)n * FW_C * FW_HW;
    const float c0 = __ldcs(img_n + hw);
    const float c1 = __ldcs(img_n + FW_HW + hw);
    const float c2 = __ldcs(img_n + 2 * FW_HW + hw);

    const float wx0 = 1.0f - fx;
    const float wy0 = 1.0f - fy;

    const int rbase = h + ix;
    const int cc = w + iy;
    const int par = cc & 1;

    uint2* __restrict__ ev_n = fw_even + (size_t)n * FW_HW;
    uint2* __restrict__ od_n = fw_odd + (size_t)n * FW_ODD_STRIDE;

    #pragma unroll
    for (int dx = 0; dx < 2; dx++) {
        const int rr = rbase + dx;
        if ((unsigned)rr >= (unsigned)FW_H) continue;
        const float wx = dx ? fx : wx0;
        const float w0 = wx * wy0;   // column cc
        const float w1 = wx * fy;    // column cc + 1
        const int rowoff = rr * FW_W;

        if ((unsigned)cc <= (unsigned)(FW_W - 2)) {
            uint2* p = par ? (od_n + rowoff + cc + 1) : (ev_n + rowoff + cc);
            red_add_v4h2(p,
                         h2u(c0 * w0, c1 * w0), h2u(c2 * w0, 0.0f),
                         h2u(c0 * w1, c1 * w1), h2u(c2 * w1, 0.0f));
        } else {
            if ((unsigned)cc < (unsigned)FW_W)
                red_add_v2h2(ev_n + rowoff + cc, h2u(c0 * w0, c1 * w0), h2u(c2 * w0, 0.0f));
            if ((unsigned)(cc + 1) < (unsigned)FW_W)
                red_add_v2h2(ev_n + rowoff + cc + 1, h2u(c0 * w1, c1 * w1), h2u(c2 * w1, 0.0f));
        }
    }
}

// ---------------- finalize: 2 px/thread, sum parity buffers -> fp32 NCHW ----------------
// Grid: (6, FW_H, 1), block 160  (6*160 = 960 = W/2 pixel-pairs per row).
__global__ __launch_bounds__(160) void fw_finalize_kernel(float* __restrict__ out, int n)
{
    const int t = blockIdx.x * 160 + threadIdx.x;   // pixel-pair index in row
    const int h = blockIdx.y;
    const int hw = h * FW_W + 2 * t;                // even pixel index

    // Even buffer: pixels hw, hw+1 are one 16B-aligned uint4.
    const uint4* ep = reinterpret_cast<const uint4*>(fw_even + (size_t)n * FW_HW + hw);
    uint4 ev;
    asm volatile("ld.global.cs.v4.u32 {%0, %1, %2, %3}, [%4];"
                 : "=r"(ev.x), "=r"(ev.y), "=r"(ev.z), "=r"(ev.w) : "l"(ep));

    // Odd buffer: elements hw+1, hw+2 (8B-aligned each).
    const uint2* op = fw_odd + ((size_t)n * FW_ODD_STRIDE + hw + 1);
    uint32_t oa, ob, oc, od;
    asm volatile("ld.global.cs.v2.u32 {%0, %1}, [%2];" : "=r"(oa), "=r"(ob) : "l"(op));
    asm volatile("ld.global.cs.v2.u32 {%0, %1}, [%2];" : "=r"(oc), "=r"(od) : "l"(op + 1));

    const float2 e0_01 = __half22float2(*reinterpret_cast<const __half2*>(&ev.x));
    const float2 e0_23 = __half22float2(*reinterpret_cast<const __half2*>(&ev.y));
    const float2 e1_01 = __half22float2(*reinterpret_cast<const __half2*>(&ev.z));
    const float2 e1_23 = __half22float2(*reinterpret_cast<const __half2*>(&ev.w));
    const float2 o0_01 = __half22float2(*reinterpret_cast<const __half2*>(&oa));
    const float2 o0_23 = __half22float2(*reinterpret_cast<const __half2*>(&ob));
    const float2 o1_01 = __half22float2(*reinterpret_cast<const __half2*>(&oc));
    const float2 o1_23 = __half22float2(*reinterpret_cast<const __half2*>(&od));

    float* __restrict__ out_n = out + (size_t)n * FW_C * FW_HW;
    const float a0 = e0_01.x + o0_01.x, b0 = e1_01.x + o1_01.x;   // c0: px0, px1
    const float a1 = e0_01.y + o0_01.y, b1 = e1_01.y + o1_01.y;   // c1
    const float a2 = e0_23.x + o0_23.x, b2 = e1_23.x + o1_23.x;   // c2

    asm volatile("st.global.cs.v2.f32 [%0], {%1, %2};"
                 :: "l"(out_n + hw),             "f"(a0), "f"(b0) : "memory");
    asm volatile("st.global.cs.v2.f32 [%0], {%1, %2};"
                 :: "l"(out_n + FW_HW + hw),     "f"(a1), "f"(b1) : "memory");
    asm volatile("st.global.cs.v2.f32 [%0], {%1, %2};"
                 :: "l"(out_n + 2 * FW_HW + hw), "f"(a2), "f"(b2) : "memory");
}

// ---------------- streams/events: created once at static init ----------------
struct FwResources {
    cudaStream_t zs;          // zero chain (high prio)
    cudaStream_t cs[FW_N];    // per-batch scatter chains (high prio)
    cudaStream_t fs;          // finalize stream (low prio)
    cudaEvent_t  root;
    cudaEvent_t  ez[FW_N];    // zero[n] done
    cudaEvent_t  es[FW_N];    // scatter[n] done
    cudaEvent_t  efin;
    FwResources() {
        int lo = 0, hi = 0;
        cudaDeviceGetStreamPriorityRange(&lo, &hi);   // hi = highest (most negative)
        cudaStreamCreateWithPriority(&zs, cudaStreamNonBlocking, hi);
        cudaStreamCreateWithPriority(&fs, cudaStreamNonBlocking, lo);
        cudaEventCreateWithFlags(&root, cudaEventDisableTiming);
        cudaEventCreateWithFlags(&efin, cudaEventDisableTiming);
        for (int i = 0; i < FW_N; i++) {
            cudaStreamCreateWithPriority(&cs[i], cudaStreamNonBlocking, hi);
            cudaEventCreateWithFlags(&ez[i], cudaEventDisableTiming);
            cudaEventCreateWithFlags(&es[i], cudaEventDisableTiming);
        }
    }
};
static FwResources g_fw;

extern "C" void kernel_launch(void* const* d_in, const int* in_sizes, int n_in,
                              void* d_out, int out_size)
{
    const float* img = (const float*)d_in[0];
    const float* flo = (const float*)d_in[1];
    float* out = (float*)d_out;

    cudaEventRecord(g_fw.root, 0);
    cudaStreamWaitEvent(g_fw.zs, g_fw.root, 0);

    // Serial zeros on zs; ez[n] gates scatter[n].
    for (int n = 0; n < FW_N; n++) {
        fw_zero_kernel<<<ZERO_BLOCKS, ZERO_THREADS, 0, g_fw.zs>>>(n);
        cudaEventRecord(g_fw.ez[n], g_fw.zs);
    }

    dim3 sgrid(FW_W / 128, FW_H, 1);
    for (int n = 0; n < FW_N; n++) {
        cudaStreamWaitEvent(g_fw.cs[n], g_fw.ez[n], 0);
        fw_scatter_kernel<<<sgrid, 128, 0, g_fw.cs[n]>>>(img, flo, n);
        cudaEventRecord(g_fw.es[n], g_fw.cs[n]);
    }

    dim3 fgrid(6, FW_H, 1);
    for (int n = 0; n < FW_N; n++) {
        cudaStreamWaitEvent(g_fw.fs, g_fw.es[n], 0);
        fw_finalize_kernel<<<fgrid, 160, 0, g_fw.fs>>>(out, n);
    }
    cudaEventRecord(g_fw.efin, g_fw.fs);
    cudaStreamWaitEvent(0, g_fw.efin, 0);
}